// round 9
// baseline (speedup 1.0000x reference)
#include <cuda_runtime.h>
#include <cuda_fp16.h>
#include <math.h>

#define N_NODES 50000
#define N_EDGES 400000
#define N_GRAPHS 512
#define F 32
#define NB 32
#define CUTOFF 5.0f
#define FULL 0xffffffffu

// ---------------- device scratch (no allocations allowed) ----------------
__device__ float g_x0[N_NODES * F];              // x0, later x0'
__device__ float g_yacc[N_NODES * F];            // segment-sum accumulator
__device__ __half g_p2h[(size_t)N_EDGES * F];    // per-edge Wr_last projection (fp16)
__device__ unsigned char g_flag[N_EDGES];        // 1 = edge inside cutoff

__device__ __forceinline__ float siluf(float x) { return x * (1.f / (1.f + __expf(-x))); }

// ---------------- K0: x0 = embed[z], yacc = x0, zero d_out -------------------
__global__ void k_init(const float* __restrict__ embed, const int* __restrict__ z,
                       float* __restrict__ out) {
    int i = blockIdx.x * blockDim.x + threadIdx.x;
    if (i < N_GRAPHS) out[i] = 0.f;
    if (i < N_NODES * F) {
        int n = i >> 5, f = i & 31;
        float v = embed[z[n] * F + f];
        g_x0[i] = v;
        g_yacc[i] = v;
    }
}

// ---------------- K1: edge pass 1 --------------------------------------------
// warp per edge, lane = feature/basis. Both matvecs fused into one packed-f32
// (fma.rn.f32x2) loop: {w01,wr} interleaved in shared, rbf duplicated into a
// per-warp shared pair buffer. ~96 issue slots/edge vs 160 scalar, ~32 regs.
__global__ void k_edge1(const float* __restrict__ pos,
                        const int* __restrict__ src, const int* __restrict__ dst,
                        const float* __restrict__ Wy0, const float* __restrict__ Wx0,
                        const float* __restrict__ Wr) {
    __shared__ float2 ws2[NB][F];                       // {w01, wr} per (basis, feature)
    __shared__ unsigned long long srbf[8][NB];          // per-warp duplicated rbf pairs
    for (int i = threadIdx.x; i < NB * F; i += blockDim.x) {
        int b = i >> 5, f = i & 31;
        ws2[b][f] = make_float2(__ldg(&Wy0[i]) + __ldg(&Wx0[i]), __ldg(&Wr[i]));
    }
    __syncthreads();

    int lane   = threadIdx.x & 31;
    int wslot  = threadIdx.x >> 5;
    int warp   = blockIdx.x * (blockDim.x >> 5) + wslot;
    int nwarps = gridDim.x * (blockDim.x >> 5);

    float lb = lgammaf((float)NB) - lgammaf((float)lane + 1.f) - lgammaf((float)NB - (float)lane);
    float kf = (float)lane;

    for (int e = warp; e < N_EDGES; e += nwarps) {
        int s = __ldg(&src[e]);
        int d = __ldg(&dst[e]);
        float dx = __ldg(&pos[s * 3 + 0]) - __ldg(&pos[d * 3 + 0]);
        float dy = __ldg(&pos[s * 3 + 1]) - __ldg(&pos[d * 3 + 1]);
        float dz = __ldg(&pos[s * 3 + 2]) - __ldg(&pos[d * 3 + 2]);
        float r = sqrtf(dx * dx + dy * dy + dz * dz + 1e-12f);
        float t = r * (1.f / CUTOFF);

        if (t >= 1.f) {                                  // rbf == 0 exactly
            if (lane == 0) g_flag[e] = 0;
            continue;
        }
        if (lane == 0) g_flag[e] = 1;
        float fc = __expf(1.f - __fdividef(1.f, fmaxf(1.f - t * t, 1e-7f)));
        float u = __fdividef(r, r + 1.f);
        u = fminf(fmaxf(u, 1e-7f), 1.f - 1e-7f);
        float rbf = __expf(lb + kf * __logf(u) + ((float)NB - 1.f - kf) * __logf(1.f - u)) * fc;

        unsigned long long rb2;
        asm("mov.b64 %0, {%1, %2};" : "=l"(rb2) : "f"(rbf), "f"(rbf));
        __syncwarp();                                    // prior iter's reads done
        srbf[wslot][lane] = rb2;                         // STS.64
        __syncwarp();

        unsigned long long pp;
        asm("mov.b64 %0, {%1, %2};" : "=l"(pp) : "f"(0.f), "f"(0.f));
#pragma unroll
        for (int b = 0; b < NB; b++) {
            unsigned long long rbp = srbf[wslot][b];     // LDS.64 broadcast
            unsigned long long wv =
                *reinterpret_cast<const unsigned long long*>(&ws2[b][lane]); // LDS.64
            asm("fma.rn.f32x2 %0, %1, %2, %0;" : "+l"(pp) : "l"(rbp), "l"(wv));
        }
        float p1, p2;
        asm("mov.b64 {%0, %1}, %2;" : "=f"(p1), "=f"(p2) : "l"(pp));

        g_p2h[(size_t)e * F + lane] = __float2half(p2);
        float msg = p1 * __ldg(&g_x0[s * F + lane]);
        atomicAdd(&g_yacc[d * F + lane], msg);
    }
}

// ---------------- K2: node update 1 (dense->silu->dense, residual) -----------
__global__ void k_node1(const float* __restrict__ W1, const float* __restrict__ b1,
                        const float* __restrict__ W2, const float* __restrict__ b2,
                        const float* __restrict__ c0) {
    __shared__ float W1s[F][F];
    __shared__ float W2s[F][F];
    for (int i = threadIdx.x; i < F * F; i += blockDim.x) {
        W1s[i >> 5][i & 31] = __ldg(&W1[i]);
        W2s[i >> 5][i & 31] = __ldg(&W2[i]);
    }
    __syncthreads();
    int lane   = threadIdx.x & 31;
    int warp   = blockIdx.x * (blockDim.x >> 5) + (threadIdx.x >> 5);
    int nwarps = gridDim.x * (blockDim.x >> 5);
    float sc  = siluf(__ldg(&c0[0]));
    float bb1 = __ldg(&b1[lane]), bb2 = __ldg(&b2[lane]);

    for (int n = warp; n < N_NODES; n += nwarps) {
        float y = g_yacc[n * F + lane];
        float y1 = bb1;
#pragma unroll
        for (int f = 0; f < F; f++) y1 = fmaf(__shfl_sync(FULL, y, f), W1s[f][lane], y1);
        float g = siluf(y1);
        float y2 = bb2;
#pragma unroll
        for (int f = 0; f < F; f++) y2 = fmaf(__shfl_sync(FULL, g, f), W2s[f][lane], y2);
        float xp = g_x0[n * F + lane] + sc * y2;
        g_x0[n * F + lane]   = xp;     // x0' for pass 2
        g_yacc[n * F + lane] = xp;     // init accumulator for y0
    }
}

// ---------------- K3: edge pass 2 — 8 edges/warp, 2 chains, float4, fp16 p2 --
__global__ void k_edge2(const int* __restrict__ src, const int* __restrict__ dst) {
    int lane   = threadIdx.x & 31;
    int g      = lane >> 3;          // edge subgroup 0..3
    int j      = lane & 7;           // feature group (4 floats each)
    int warp   = blockIdx.x * (blockDim.x >> 5) + (threadIdx.x >> 5);
    int nwarps = gridDim.x * (blockDim.x >> 5);

    for (int e0 = warp * 8; e0 < N_EDGES; e0 += nwarps * 8) {
        unsigned long long fl8 = *reinterpret_cast<const unsigned long long*>(&g_flag[e0]);
        if (!fl8) continue;                                   // all 8 dead
        int sd = 0;
        if (lane < 16) sd = __ldg(lane < 8 ? &src[e0 + lane] : &dst[e0 + (lane - 8)]);
        // edge A = e0+g (flags bytes 0..3), edge B = e0+4+g (bytes 4..7)
        int sA = __shfl_sync(FULL, sd, g);
        int dA = __shfl_sync(FULL, sd, 8 + g);
        int sB = __shfl_sync(FULL, sd, 4 + g);
        int dB = __shfl_sync(FULL, sd, 12 + g);
        bool fA = (fl8 >> (8 * g)) & 0xff;
        bool fB = (fl8 >> (8 * (4 + g))) & 0xff;

        float4 mA, mB;                 // issue both gather chains before both REDs
        if (fA) {
            uint2 u = *reinterpret_cast<const uint2*>(&g_p2h[(size_t)(e0 + g) * F + j * 4]);
            float2 a = __half22float2(*reinterpret_cast<__half2*>(&u.x));
            float2 b = __half22float2(*reinterpret_cast<__half2*>(&u.y));
            float4 xv = *reinterpret_cast<const float4*>(&g_x0[(size_t)sA * F + j * 4]);
            mA = make_float4(a.x * xv.x, a.y * xv.y, b.x * xv.z, b.y * xv.w);
        }
        if (fB) {
            uint2 u = *reinterpret_cast<const uint2*>(&g_p2h[(size_t)(e0 + 4 + g) * F + j * 4]);
            float2 a = __half22float2(*reinterpret_cast<__half2*>(&u.x));
            float2 b = __half22float2(*reinterpret_cast<__half2*>(&u.y));
            float4 xv = *reinterpret_cast<const float4*>(&g_x0[(size_t)sB * F + j * 4]);
            mB = make_float4(a.x * xv.x, a.y * xv.y, b.x * xv.z, b.y * xv.w);
        }
        if (fA) atomicAdd(reinterpret_cast<float4*>(&g_yacc[(size_t)dA * F + j * 4]), mA);
        if (fB) atomicAdd(reinterpret_cast<float4*>(&g_yacc[(size_t)dB * F + j * 4]), mB);
    }
}

// ---------------- K4: node update 2 + readout, scatter straight to d_out -----
__global__ void k_node2(const float* __restrict__ W11, const float* __restrict__ b11,
                        const float* __restrict__ W21, const float* __restrict__ b21,
                        const float* __restrict__ c1,
                        const float* __restrict__ Wro1, const float* __restrict__ bro1,
                        const float* __restrict__ Wro2, const float* __restrict__ bro2,
                        const float* __restrict__ abias, const int* __restrict__ z,
                        const int* __restrict__ bseg, float* __restrict__ out) {
    __shared__ float W11s[F][F];
    __shared__ float W21s[F][F];
    __shared__ float Wro1s[F][F];
    for (int i = threadIdx.x; i < F * F; i += blockDim.x) {
        W11s[i >> 5][i & 31]  = __ldg(&W11[i]);
        W21s[i >> 5][i & 31]  = __ldg(&W21[i]);
        Wro1s[i >> 5][i & 31] = __ldg(&Wro1[i]);
    }
    __syncthreads();
    int lane   = threadIdx.x & 31;
    int warp   = blockIdx.x * (blockDim.x >> 5) + (threadIdx.x >> 5);
    int nwarps = gridDim.x * (blockDim.x >> 5);
    float sc   = siluf(__ldg(&c1[0]));
    float w2c  = __ldg(&Wro2[lane]);
    float bb11 = __ldg(&b11[lane]), bb21 = __ldg(&b21[lane]), bbr = __ldg(&bro1[lane]);
    float br2  = __ldg(&bro2[0]);

    for (int n = warp; n < N_NODES; n += nwarps) {
        float y0 = g_yacc[n * F + lane];
        float a = bb11;
#pragma unroll
        for (int f = 0; f < F; f++) a = fmaf(__shfl_sync(FULL, y0, f), W11s[f][lane], a);
        a = siluf(a);
        float yb = bb21;
#pragma unroll
        for (int f = 0; f < F; f++) yb = fmaf(__shfl_sync(FULL, a, f), W21s[f][lane], yb);
        float xs0 = g_x0[n * F + lane] + sc * yb;
        float h = bbr;
#pragma unroll
        for (int f = 0; f < F; f++) h = fmaf(__shfl_sync(FULL, xs0, f), Wro1s[f][lane], h);
        h = siluf(h);
        float part = h * w2c;
#pragma unroll
        for (int off = 16; off; off >>= 1) part += __shfl_xor_sync(FULL, part, off);
        if (lane == 0) {
            float ea = part + br2 + __ldg(&abias[z[n]]);
            atomicAdd(&out[bseg[n]], ea);
        }
    }
}

// ---------------- launch ------------------------------------------------------
extern "C" void kernel_launch(void* const* d_in, const int* in_sizes, int n_in,
                              void* d_out, int out_size) {
    const float* positions  = (const float*)d_in[0];
    const float* embed      = (const float*)d_in[1];
    const float* Wy0        = (const float*)d_in[2];
    const float* Wx0        = (const float*)d_in[3];
    const float* W1_0       = (const float*)d_in[4];
    const float* b1_0       = (const float*)d_in[5];
    const float* W2_0       = (const float*)d_in[6];
    const float* b2_0       = (const float*)d_in[7];
    const float* c0         = (const float*)d_in[8];
    const float* Wr_last    = (const float*)d_in[9];
    const float* W1_1       = (const float*)d_in[10];
    const float* b1_1       = (const float*)d_in[11];
    const float* W2_1       = (const float*)d_in[12];
    const float* b2_1       = (const float*)d_in[13];
    const float* c1         = (const float*)d_in[14];
    const float* Wro1       = (const float*)d_in[15];
    const float* bro1       = (const float*)d_in[16];
    const float* Wro2       = (const float*)d_in[17];
    const float* bro2       = (const float*)d_in[18];
    const float* abias      = (const float*)d_in[19];
    const int*   z          = (const int*)d_in[20];
    const int*   dst_idx    = (const int*)d_in[21];
    const int*   src_idx    = (const int*)d_in[22];
    const int*   bseg       = (const int*)d_in[23];
    float*       out        = (float*)d_out;

    k_init<<<(N_NODES * F + 255) / 256, 256>>>(embed, z, out);
    k_edge1<<<2048, 256>>>(positions, src_idx, dst_idx, Wy0, Wx0, Wr_last);
    k_node1<<<1024, 256>>>(W1_0, b1_0, W2_0, b2_0, c0);
    k_edge2<<<2048, 256>>>(src_idx, dst_idx);
    k_node2<<<1024, 256>>>(W1_1, b1_1, W2_1, b2_1, c1,
                           Wro1, bro1, Wro2, bro2, abias, z, bseg, out);
}

// round 10
// speedup vs baseline: 1.5921x; 1.5921x over previous
#include <cuda_runtime.h>
#include <cuda_fp16.h>
#include <math.h>

#define N_NODES 50000
#define N_EDGES 400000
#define N_GRAPHS 512
#define F 32
#define NB 32
#define CUTOFF 5.0f
#define FULL 0xffffffffu

// ---------------- device scratch (no allocations allowed) ----------------
__device__ float g_x0[N_NODES * F];              // x0, later x0'
__device__ float g_yacc[N_NODES * F];            // segment-sum accumulator
__device__ __half g_p2h[(size_t)N_EDGES * F];    // per-edge Wr_last projection (fp16)
__device__ unsigned char g_flag[N_EDGES];        // 1 = edge inside cutoff

__device__ __forceinline__ float siluf(float x) { return x * (1.f / (1.f + __expf(-x))); }

// ---------------- K0: x0 = embed[z], yacc = x0, zero d_out -------------------
__global__ void k_init(const float* __restrict__ embed, const int* __restrict__ z,
                       float* __restrict__ out) {
    int i = blockIdx.x * blockDim.x + threadIdx.x;
    if (i < N_GRAPHS) out[i] = 0.f;
    if (i < N_NODES * F) {
        int n = i >> 5, f = i & 31;
        float v = embed[z[n] * F + f];
        g_x0[i] = v;
        g_yacc[i] = v;
    }
}

// ---------------- K1: edge pass 1 (R3 structure, packed float2 weights) ------
// warp per edge, lane = feature/basis. Matvec iteration: SHFL + LDS.64 + 2 FFMA.
__global__ void k_edge1(const float* __restrict__ pos,
                        const int* __restrict__ src, const int* __restrict__ dst,
                        const float* __restrict__ Wy0, const float* __restrict__ Wx0,
                        const float* __restrict__ Wr) {
    __shared__ float2 ws2[NB][F];                 // {w01, wr} per (basis, feature)
    for (int i = threadIdx.x; i < NB * F; i += blockDim.x) {
        int b = i >> 5, f = i & 31;
        ws2[b][f] = make_float2(__ldg(&Wy0[i]) + __ldg(&Wx0[i]), __ldg(&Wr[i]));
    }
    __syncthreads();

    int lane   = threadIdx.x & 31;
    int warp   = blockIdx.x * (blockDim.x >> 5) + (threadIdx.x >> 5);
    int nwarps = gridDim.x * (blockDim.x >> 5);

    float lb = lgammaf((float)NB) - lgammaf((float)lane + 1.f) - lgammaf((float)NB - (float)lane);
    float kf = (float)lane;

    for (int e = warp; e < N_EDGES; e += nwarps) {
        int s = __ldg(&src[e]);
        int d = __ldg(&dst[e]);
        float dx = __ldg(&pos[s * 3 + 0]) - __ldg(&pos[d * 3 + 0]);
        float dy = __ldg(&pos[s * 3 + 1]) - __ldg(&pos[d * 3 + 1]);
        float dz = __ldg(&pos[s * 3 + 2]) - __ldg(&pos[d * 3 + 2]);
        float r = sqrtf(dx * dx + dy * dy + dz * dz + 1e-12f);
        float t = r * (1.f / CUTOFF);

        if (t >= 1.f) {                           // rbf == 0 exactly past cutoff
            if (lane == 0) g_flag[e] = 0;
            continue;
        }
        if (lane == 0) g_flag[e] = 1;
        float fc = __expf(1.f - __fdividef(1.f, fmaxf(1.f - t * t, 1e-7f)));
        float u = __fdividef(r, r + 1.f);
        u = fminf(fmaxf(u, 1e-7f), 1.f - 1e-7f);
        float rbf = __expf(lb + kf * __logf(u) + ((float)NB - 1.f - kf) * __logf(1.f - u)) * fc;

        float p1 = 0.f, p2 = 0.f;
#pragma unroll
        for (int b = 0; b < NB; b++) {
            float rb = __shfl_sync(FULL, rbf, b);
            float2 w = ws2[b][lane];              // single LDS.64
            p1 = fmaf(rb, w.x, p1);
            p2 = fmaf(rb, w.y, p2);
        }
        g_p2h[(size_t)e * F + lane] = __float2half(p2);
        float msg = p1 * __ldg(&g_x0[s * F + lane]);
        atomicAdd(&g_yacc[d * F + lane], msg);
    }
}

// ---------------- K2: node update 1 (dense->silu->dense, residual) -----------
__global__ void k_node1(const float* __restrict__ W1, const float* __restrict__ b1,
                        const float* __restrict__ W2, const float* __restrict__ b2,
                        const float* __restrict__ c0) {
    __shared__ float W1s[F][F];
    __shared__ float W2s[F][F];
    for (int i = threadIdx.x; i < F * F; i += blockDim.x) {
        W1s[i >> 5][i & 31] = __ldg(&W1[i]);
        W2s[i >> 5][i & 31] = __ldg(&W2[i]);
    }
    __syncthreads();
    int lane   = threadIdx.x & 31;
    int warp   = blockIdx.x * (blockDim.x >> 5) + (threadIdx.x >> 5);
    int nwarps = gridDim.x * (blockDim.x >> 5);
    float sc  = siluf(__ldg(&c0[0]));
    float bb1 = __ldg(&b1[lane]), bb2 = __ldg(&b2[lane]);

    for (int n = warp; n < N_NODES; n += nwarps) {
        float y = g_yacc[n * F + lane];
        float y1 = bb1;
#pragma unroll
        for (int f = 0; f < F; f++) y1 = fmaf(__shfl_sync(FULL, y, f), W1s[f][lane], y1);
        float g = siluf(y1);
        float y2 = bb2;
#pragma unroll
        for (int f = 0; f < F; f++) y2 = fmaf(__shfl_sync(FULL, g, f), W2s[f][lane], y2);
        float xp = g_x0[n * F + lane] + sc * y2;
        g_x0[n * F + lane]   = xp;     // x0' for pass 2
        g_yacc[n * F + lane] = xp;     // init accumulator for y0
    }
}

// ---------------- K3: edge pass 2 — 8 edges/warp, 2 chains, float4, fp16 p2 --
__global__ void k_edge2(const int* __restrict__ src, const int* __restrict__ dst) {
    int lane   = threadIdx.x & 31;
    int g      = lane >> 3;          // edge subgroup 0..3
    int j      = lane & 7;           // feature group (4 floats each)
    int warp   = blockIdx.x * (blockDim.x >> 5) + (threadIdx.x >> 5);
    int nwarps = gridDim.x * (blockDim.x >> 5);

    for (int e0 = warp * 8; e0 < N_EDGES; e0 += nwarps * 8) {
        unsigned long long fl8 = *reinterpret_cast<const unsigned long long*>(&g_flag[e0]);
        if (!fl8) continue;                                   // all 8 dead
        int sd = 0;
        if (lane < 16) sd = __ldg(lane < 8 ? &src[e0 + lane] : &dst[e0 + (lane - 8)]);
        int sA = __shfl_sync(FULL, sd, g);
        int dA = __shfl_sync(FULL, sd, 8 + g);
        int sB = __shfl_sync(FULL, sd, 4 + g);
        int dB = __shfl_sync(FULL, sd, 12 + g);
        bool fA = (fl8 >> (8 * g)) & 0xff;
        bool fB = (fl8 >> (8 * (4 + g))) & 0xff;

        float4 mA, mB;                 // issue both gather chains before both REDs
        if (fA) {
            uint2 u = *reinterpret_cast<const uint2*>(&g_p2h[(size_t)(e0 + g) * F + j * 4]);
            float2 a = __half22float2(*reinterpret_cast<__half2*>(&u.x));
            float2 b = __half22float2(*reinterpret_cast<__half2*>(&u.y));
            float4 xv = *reinterpret_cast<const float4*>(&g_x0[(size_t)sA * F + j * 4]);
            mA = make_float4(a.x * xv.x, a.y * xv.y, b.x * xv.z, b.y * xv.w);
        }
        if (fB) {
            uint2 u = *reinterpret_cast<const uint2*>(&g_p2h[(size_t)(e0 + 4 + g) * F + j * 4]);
            float2 a = __half22float2(*reinterpret_cast<__half2*>(&u.x));
            float2 b = __half22float2(*reinterpret_cast<__half2*>(&u.y));
            float4 xv = *reinterpret_cast<const float4*>(&g_x0[(size_t)sB * F + j * 4]);
            mB = make_float4(a.x * xv.x, a.y * xv.y, b.x * xv.z, b.y * xv.w);
        }
        if (fA) atomicAdd(reinterpret_cast<float4*>(&g_yacc[(size_t)dA * F + j * 4]), mA);
        if (fB) atomicAdd(reinterpret_cast<float4*>(&g_yacc[(size_t)dB * F + j * 4]), mB);
    }
}

// ---------------- K4: node update 2 + readout, scatter straight to d_out -----
__global__ void k_node2(const float* __restrict__ W11, const float* __restrict__ b11,
                        const float* __restrict__ W21, const float* __restrict__ b21,
                        const float* __restrict__ c1,
                        const float* __restrict__ Wro1, const float* __restrict__ bro1,
                        const float* __restrict__ Wro2, const float* __restrict__ bro2,
                        const float* __restrict__ abias, const int* __restrict__ z,
                        const int* __restrict__ bseg, float* __restrict__ out) {
    __shared__ float W11s[F][F];
    __shared__ float W21s[F][F];
    __shared__ float Wro1s[F][F];
    for (int i = threadIdx.x; i < F * F; i += blockDim.x) {
        W11s[i >> 5][i & 31]  = __ldg(&W11[i]);
        W21s[i >> 5][i & 31]  = __ldg(&W21[i]);
        Wro1s[i >> 5][i & 31] = __ldg(&Wro1[i]);
    }
    __syncthreads();
    int lane   = threadIdx.x & 31;
    int warp   = blockIdx.x * (blockDim.x >> 5) + (threadIdx.x >> 5);
    int nwarps = gridDim.x * (blockDim.x >> 5);
    float sc   = siluf(__ldg(&c1[0]));
    float w2c  = __ldg(&Wro2[lane]);
    float bb11 = __ldg(&b11[lane]), bb21 = __ldg(&b21[lane]), bbr = __ldg(&bro1[lane]);
    float br2  = __ldg(&bro2[0]);

    for (int n = warp; n < N_NODES; n += nwarps) {
        float y0 = g_yacc[n * F + lane];
        float a = bb11;
#pragma unroll
        for (int f = 0; f < F; f++) a = fmaf(__shfl_sync(FULL, y0, f), W11s[f][lane], a);
        a = siluf(a);
        float yb = bb21;
#pragma unroll
        for (int f = 0; f < F; f++) yb = fmaf(__shfl_sync(FULL, a, f), W21s[f][lane], yb);
        float xs0 = g_x0[n * F + lane] + sc * yb;
        float h = bbr;
#pragma unroll
        for (int f = 0; f < F; f++) h = fmaf(__shfl_sync(FULL, xs0, f), Wro1s[f][lane], h);
        h = siluf(h);
        float part = h * w2c;
#pragma unroll
        for (int off = 16; off; off >>= 1) part += __shfl_xor_sync(FULL, part, off);
        if (lane == 0) {
            float ea = part + br2 + __ldg(&abias[z[n]]);
            atomicAdd(&out[bseg[n]], ea);
        }
    }
}

// ---------------- launch ------------------------------------------------------
extern "C" void kernel_launch(void* const* d_in, const int* in_sizes, int n_in,
                              void* d_out, int out_size) {
    const float* positions  = (const float*)d_in[0];
    const float* embed      = (const float*)d_in[1];
    const float* Wy0        = (const float*)d_in[2];
    const float* Wx0        = (const float*)d_in[3];
    const float* W1_0       = (const float*)d_in[4];
    const float* b1_0       = (const float*)d_in[5];
    const float* W2_0       = (const float*)d_in[6];
    const float* b2_0       = (const float*)d_in[7];
    const float* c0         = (const float*)d_in[8];
    const float* Wr_last    = (const float*)d_in[9];
    const float* W1_1       = (const float*)d_in[10];
    const float* b1_1       = (const float*)d_in[11];
    const float* W2_1       = (const float*)d_in[12];
    const float* b2_1       = (const float*)d_in[13];
    const float* c1         = (const float*)d_in[14];
    const float* Wro1       = (const float*)d_in[15];
    const float* bro1       = (const float*)d_in[16];
    const float* Wro2       = (const float*)d_in[17];
    const float* bro2       = (const float*)d_in[18];
    const float* abias      = (const float*)d_in[19];
    const int*   z          = (const int*)d_in[20];
    const int*   dst_idx    = (const int*)d_in[21];
    const int*   src_idx    = (const int*)d_in[22];
    const int*   bseg       = (const int*)d_in[23];
    float*       out        = (float*)d_out;

    k_init<<<(N_NODES * F + 255) / 256, 256>>>(embed, z, out);
    k_edge1<<<2048, 256>>>(positions, src_idx, dst_idx, Wy0, Wx0, Wr_last);
    k_node1<<<1024, 256>>>(W1_0, b1_0, W2_0, b2_0, c0);
    k_edge2<<<2048, 256>>>(src_idx, dst_idx);
    k_node2<<<1024, 256>>>(W1_1, b1_1, W2_1, b2_1, c1,
                           Wro1, bro1, Wro2, bro2, abias, z, bseg, out);
}